// round 10
// baseline (speedup 1.0000x reference)
#include <cuda_runtime.h>
#include <math.h>

#define NBLK 128
#define NTHR 256
#define GSIZE 16              // blocks per dependency group (== COLBLKS of ph1)
#define NGRP (NBLK / GSIZE)
#define BB 64
#define TT 512
#define HH 512

// Scratch (static __device__ arrays: allocation-free per harness rules)
__device__ float g_buf0[(size_t)TT * BB * HH];   // layer0 output, time-major [T][B][H]
__device__ float g_buf1[(size_t)TT * BB * HH];   // layer1 output, time-major
__device__ float g_h[4 * BB * HH];               // hidden state, up to R=256 rows
__device__ float g_rh[4 * BB * HH];              // r * h
__device__ float g_u[4 * BB * HH];               // update gate

// Per-group barrier cells, one 128B line each (no cross-group contention).
struct alignas(128) GBar { unsigned int cnt; unsigned int gen; unsigned int pad[30]; };
__device__ GBar g_gbar[NGRP];

// Pre-packed weights: Wp[k/2][c] = (W[k][c], W[k+1][c]) so the f32x2 FMA
// multiplier pair arrives in one LDG.64 with no packing MOVs in the hot loop.
__device__ float2 g_gk0p[(768 * 1024) / 2];
__device__ float2 g_ck0p[(768 * 512) / 2];
__device__ float2 g_gk1p[(1024 * 1024) / 2];
__device__ float2 g_ck1p[(1024 * 512) / 2];
__device__ float2 g_gk2p[(1024 * 1024) / 2];
__device__ float2 g_ck2p[(1024 * 512) / 2];

__device__ __forceinline__ unsigned long long fma2(unsigned long long a,
                                                   unsigned long long b,
                                                   unsigned long long c) {
    unsigned long long d;
    asm("fma.rn.f32x2 %0, %1, %2, %3;" : "=l"(d) : "l"(a), "l"(b), "l"(c));
    return d;
}

__global__ void pack_weights_kernel(const float* __restrict__ W,
                                    float2* __restrict__ Wp, int K2, int N) {
    for (int idx = blockIdx.x * blockDim.x + threadIdx.x; idx < K2 * N;
         idx += gridDim.x * blockDim.x) {
        const int kk2 = idx / N;
        const int c   = idx - kk2 * N;
        Wp[idx] = make_float2(W[(2 * kk2) * N + c], W[(2 * kk2 + 1) * N + c]);
    }
}

// Split-phase PER-GROUP barrier (16 blocks sharing the same GRU rows) with
// scoped release/acquire — deliberately NO __threadfence(): a gpu-scope fence
// emits CCTL.IVALL on sm_103a, flushing L1. Cross-CTA mutable data
// (g_h/g_rh/g_u) is accessed L2-only (__ldcg/__stcg), so no acquire-side L1
// invalidation is ever needed. Release chain: CTA stores -> bar.sync ->
// thread-0 atom.release -> peer ld.acquire (morally strong per PTX model).
// Between bar_arrive() and bar_wait() a block may do work that reads only
// immutable inputs and writes only its own SMEM (x prestaging).
struct BarTok { unsigned int g; int last; };

__device__ __forceinline__ BarTok bar_arrive() {
    __syncthreads();
    BarTok tk; tk.g = 0; tk.last = 0;
    if (threadIdx.x == 0) {
        GBar* bar = &g_gbar[blockIdx.x / GSIZE];
        unsigned int g;
        // must read generation BEFORE arrival (else last-arriver race)
        asm volatile("ld.acquire.gpu.global.u32 %0, [%1];"
                     : "=r"(g) : "l"(&bar->gen));
        unsigned int t;
        asm volatile("atom.release.gpu.global.add.u32 %0, [%1], 1;"
                     : "=r"(t) : "l"(&bar->cnt));
        if (t == GSIZE - 1) {
            asm volatile("st.relaxed.gpu.global.u32 [%0], %1;"
                         :: "l"(&bar->cnt), "r"(0u));
            asm volatile("red.release.gpu.global.add.u32 [%0], %1;"
                         :: "l"(&bar->gen), "r"(1u));
            tk.last = 1;
        }
        tk.g = g;
    }
    return tk;
}

__device__ __forceinline__ void bar_wait(BarTok tk) {
    if (threadIdx.x == 0 && !tk.last) {
        GBar* bar = &g_gbar[blockIdx.x / GSIZE];
        unsigned int cur;
        do {
            asm volatile("ld.acquire.gpu.global.u32 %0, [%1];"
                         : "=r"(cur) : "l"(&bar->gen));
        } while (cur == tk.g);
    }
    __syncthreads();
}

__device__ __forceinline__ float sigmoidf_fast(float x) {
    return __fdividef(1.0f, 1.0f + __expf(-x));
}
// Branchless fast tanh via __expf; clamp keeps e finite (exp(30) ~ 1e13).
__device__ __forceinline__ float tanhf_fast(float x) {
    const float xc = fminf(fmaxf(x, -15.0f), 15.0f);
    const float e  = __expf(2.0f * xc);
    return __fdividef(e - 1.0f, e + 1.0f);
}

// Prestage the x-columns of ALL of this block's job tiles (NBUF operand
// buffers) into smem. Safe between bar_arrive/bar_wait: reads immutable x,
// writes own SMEM only.
template<int DIN, int RATE, int RB, int CC, int N, int NBUF>
__device__ __forceinline__ void prestage_x(
    const float* __restrict__ xin, long long xs_t, long long xs_b,
    int s, float* smem)
{
    constexpr int K = DIN + HH;
    constexpr int COLBLKS = N / CC;
    constexpr int NJOBS = (RATE * BB / RB) * COLBLKS;
    constexpr int DINV = DIN / 4;
    #pragma unroll
    for (int jb = 0; jb < NBUF; jb++) {
        const int job = blockIdx.x + jb * NBLK;
        if (job >= NJOBS) break;
        const int rowbase = (job / COLBLKS) * RB;
        float* buf = smem + jb * RB * K;
        for (int idx = threadIdx.x; idx < RB * DINV; idx += NTHR) {
            const int i = idx / DINV;
            const int k = (idx - i * DINV) * 4;
            const int j = rowbase + i;
            const int t = s * RATE + (j >> 6);
            const int b = j & 63;
            const float4 v = *reinterpret_cast<const float4*>(
                    &xin[(long long)t * xs_t + (long long)b * xs_b + k]);
            *reinterpret_cast<float4*>(&buf[i * K + k]) = v;
        }
    }
}

// Zero this block's own job rows of g_h (duplicated across the 16 blocks of
// a group — benign concurrent zero-writes, one-time cost).
template<int RB, int COLBLKS, int NJOBS>
__device__ __forceinline__ void zero_h_rows() {
    for (int job = blockIdx.x; job < NJOBS; job += NBLK) {
        const int rowbase = (job / COLBLKS) * RB;
        for (int idx = threadIdx.x; idx < RB * HH / 4; idx += NTHR)
            __stcg(reinterpret_cast<float4*>(&g_h[rowbase * HH + idx * 4]),
                   make_float4(0.f, 0.f, 0.f, 0.f));
    }
}

// One GRU phase as a tiled (R x N) = (R x K) @ (K x N) with fused epilogue.
// PHASE 1: gates (N=1024), operand = [x_t | h].   Writes g_rh (n<512), g_u.
// PHASE 2: candidate (N=512), operand = [x_t | r*h]. Writes h, out.
// Block job = RB rows x CC cols; 8 warps = CW column-warps x (8/CW) K-slices.
// CPT: output columns per thread (1 or 2). W-duplication over L2 = R/RB per
// step, so RB is chosen to keep LTS time under the FMA time of each phase.
// NBUF: operand buffers (== jobs per block); each job jb uses buffer jb, so
// all jobs' x-columns can be prestaged during the preceding barrier.
// XMODE: 0 = stage everything; 1 = x of ALL jobs prestaged (per-buffer);
// 2 = operand x already in buffer 0 from the previous phase (same rowblock +
// K layout; layer-1 ph2 only).
template<int DIN, int RATE, int RB, int CC, int CW, int CPT, int NBUF, int N,
         int PHASE, int XMODE>
__device__ __forceinline__ void run_phase(
    const float* __restrict__ xin, long long xs_t, long long xs_b,
    const float2* __restrict__ Wp, const float* __restrict__ bias,
    float* __restrict__ out, long long os_t, long long os_b,
    int s, float* smem)
{
    constexpr int K = DIN + HH;
    constexpr int R = RATE * BB;
    constexpr int KS = 8 / CW;
    constexpr int KC = K / KS;
    constexpr int ROWBLKS = R / RB;
    constexpr int COLBLKS = N / CC;
    constexpr int NJOBS = ROWBLKS * COLBLKS;
    constexpr int KV = K / 4;
    constexpr int HV = HH / 4;
    constexpr int CCV = CC / 4;
    constexpr int WCOLS = 32 * CPT;          // columns per warp
    static_assert(CW * WCOLS == CC, "warp columns must tile CC");
    static_assert(NJOBS <= NBUF * NBLK, "jobs must fit operand buffers");

    float* smem_red = smem + NBUF * RB * K;  // after all operand buffers

    const float* hsrc = (PHASE == 1) ? g_h : g_rh;
    const int tid  = threadIdx.x;
    const int lane = tid & 31;
    const int w    = tid >> 5;
    const int cw   = w % CW;
    const int ksid = w / CW;

    int jb = 0;
    for (int job = blockIdx.x; job < NJOBS; job += NBLK, jb++) {
        const int rb = job / COLBLKS;
        const int cb = job - rb * COLBLKS;
        const int rowbase = rb * RB;
        const int colbase = cb * CC;
        float* smem_op = smem + jb * RB * K;

        const bool skipx = (XMODE >= 1);

        // Stage operand rows [x | h-or-rh] into SMEM, float4-vectorized.
        // h/rh are cross-CTA mutable -> L2-only loads (__ldcg).
        // x is immutable within this launch -> normal cached load.
        if (skipx) {
            // x columns already in this job's buffer; stage only h/rh.
            for (int idx = tid; idx < RB * HV; idx += NTHR) {
                const int i = idx / HV;
                const int kh = (idx - i * HV) * 4;
                const int j = rowbase + i;
                const float4 v = __ldcg(reinterpret_cast<const float4*>(
                        &hsrc[j * HH + kh]));
                *reinterpret_cast<float4*>(&smem_op[i * K + DIN + kh]) = v;
            }
        } else {
            for (int idx = tid; idx < RB * KV; idx += NTHR) {
                const int i = idx / KV;
                const int k = (idx - i * KV) * 4;
                const int j = rowbase + i;
                float4 v;
                if (k < DIN) {
                    const int t = s * RATE + (j >> 6);
                    const int b = j & 63;
                    v = *reinterpret_cast<const float4*>(
                            &xin[(long long)t * xs_t + (long long)b * xs_b + k]);
                } else {
                    v = __ldcg(reinterpret_cast<const float4*>(
                            &hsrc[j * HH + (k - DIN)]));
                }
                *reinterpret_cast<float4*>(&smem_op[i * K + k]) = v;
            }
        }
        __syncthreads();

        // Packed-f32x2 dot: each lane owns CPT output columns, RB rows.
        // NOTE: W tiles (>=196KB) exceed usable L1, so W streams from L2
        // every step on every layer; RB choices keep that stream under the
        // FMA time. (First profile: check lts vs fma.)
        {
            const int c = colbase + cw * WCOLS + lane;
            const int k0 = ksid * KC;
            const unsigned long long* wq =
                reinterpret_cast<const unsigned long long*>(Wp) +
                (long long)(k0 >> 1) * N + c;
            unsigned long long acc[RB * CPT];
            #pragma unroll
            for (int i = 0; i < RB * CPT; i++) acc[i] = 0ULL;
            #pragma unroll 4
            for (int kk = 0; kk < KC; kk += 4) {
                const unsigned long long wp0 = wq[0];
                const unsigned long long wp1 = wq[N];
                unsigned long long wp2 = 0, wp3 = 0;
                if (CPT == 2) { wp2 = wq[32]; wp3 = wq[N + 32]; }
                wq += 2 * N;
                const float* sop = smem_op + k0 + kk;
                #pragma unroll
                for (int i = 0; i < RB; i++) {
                    const ulonglong2 op =
                        *reinterpret_cast<const ulonglong2*>(sop + i * K);
                    acc[i * CPT] = fma2(op.x, wp0, acc[i * CPT]);
                    acc[i * CPT] = fma2(op.y, wp1, acc[i * CPT]);
                    if (CPT == 2) {
                        acc[i * CPT + 1] = fma2(op.x, wp2, acc[i * CPT + 1]);
                        acc[i * CPT + 1] = fma2(op.y, wp3, acc[i * CPT + 1]);
                    }
                }
            }
            #pragma unroll
            for (int i = 0; i < RB; i++) {
                #pragma unroll
                for (int p = 0; p < CPT; p++) {
                    const unsigned long long a = acc[i * CPT + p];
                    const float lo = __uint_as_float((unsigned int)(a & 0xffffffffull));
                    const float hi = __uint_as_float((unsigned int)(a >> 32));
                    smem_red[(ksid * RB + i) * CC + cw * WCOLS + p * 32 + lane] =
                        lo + hi;
                }
            }
        }
        __syncthreads();

        // Reduce across K-slices + fused epilogue (float4-vectorized).
        for (int idx = tid; idx < RB * CCV; idx += NTHR) {
            const int i  = idx / CCV;
            const int cc = (idx - i * CCV) * 4;
            float4 dot = make_float4(0.f, 0.f, 0.f, 0.f);
            #pragma unroll
            for (int q = 0; q < KS; q++) {
                const float4 r = *reinterpret_cast<const float4*>(
                        &smem_red[(q * RB + i) * CC + cc]);
                dot.x += r.x; dot.y += r.y; dot.z += r.z; dot.w += r.w;
            }
            const int n = colbase + cc;
            const int j = rowbase + i;
            const float4 bv = *reinterpret_cast<const float4*>(&bias[n]);
            dot.x += bv.x; dot.y += bv.y; dot.z += bv.z; dot.w += bv.w;
            if (PHASE == 1) {
                float4 g;
                g.x = sigmoidf_fast(dot.x); g.y = sigmoidf_fast(dot.y);
                g.z = sigmoidf_fast(dot.z); g.w = sigmoidf_fast(dot.w);
                if (n < HH) {
                    const float4 hv = __ldcg(reinterpret_cast<const float4*>(
                            &g_h[j * HH + n]));
                    float4 rh;
                    rh.x = g.x * hv.x; rh.y = g.y * hv.y;
                    rh.z = g.z * hv.z; rh.w = g.w * hv.w;
                    __stcg(reinterpret_cast<float4*>(&g_rh[j * HH + n]), rh);
                } else {
                    __stcg(reinterpret_cast<float4*>(&g_u[j * HH + (n - HH)]), g);
                }
            } else {
                float4 cand;
                cand.x = tanhf_fast(dot.x); cand.y = tanhf_fast(dot.y);
                cand.z = tanhf_fast(dot.z); cand.w = tanhf_fast(dot.w);
                const float4 uu = __ldcg(reinterpret_cast<const float4*>(
                        &g_u[j * HH + n]));
                const float4 hv = __ldcg(reinterpret_cast<const float4*>(
                        &g_h[j * HH + n]));
                float4 hn;
                hn.x = uu.x * hv.x + (1.0f - uu.x) * cand.x;
                hn.y = uu.y * hv.y + (1.0f - uu.y) * cand.y;
                hn.z = uu.z * hv.z + (1.0f - uu.z) * cand.z;
                hn.w = uu.w * hv.w + (1.0f - uu.w) * cand.w;
                __stcg(reinterpret_cast<float4*>(&g_h[j * HH + n]), hn);
                const int t = s * RATE + (j >> 6);
                const int b = j & 63;
                *reinterpret_cast<float4*>(
                    &out[(long long)t * os_t + (long long)b * os_b + n]) = hn;
            }
        }
        // Trailing sync only needed if another job will reuse smem_red in
        // THIS phase; the phase-ending bar_arrive() issues its own bar.sync.
        if (job + NBLK < NJOBS) __syncthreads();
    }
}

// PH2X: XMODE for phase 2 (layer1 = 2: x reused from ph1's smem; else 1).
// Group-consistency (verified per layer): the blocks touching a given set of
// GRU rows are exactly one group of GSIZE=16 consecutive blocks, in BOTH
// phases, including layer-2's two-job mapping:
//  k0: ph1 RB8/CC64 rows[8g,8g+8)    == ph2 RB8/CC32 rows[8g,8g+8)
//  k1: ph1 RB16/CC64 rows[16g,·)     == ph2 RB16/CC32 rows[16g,·)
//  k2: ph1 RB16/CC64 jobs b,b+128 -> rows[16g,·)U[128+16g,·)
//      ph2 RB16/CC32 jobs b,b+128 -> rows[16g,·)U[128+16g,·)  (same union)
template<int DIN, int RATE,
         int RB1, int CC1, int CW1, int CPT1,
         int RB2, int CC2, int CW2, int CPT2, int PH2X>
__global__ void __launch_bounds__(NTHR, 1) layer_kernel(
    const float* __restrict__ xin, long long xs_t, long long xs_b,
    const float2* __restrict__ gkp, const float* __restrict__ gb,
    const float2* __restrict__ ckp, const float* __restrict__ cb,
    float* __restrict__ out, long long os_t, long long os_b)
{
    extern __shared__ float smem[];
    constexpr int R = RATE * BB;
    constexpr int S = TT / RATE;
    constexpr int COLBLKS1 = 1024 / CC1;
    constexpr int NJOBS1 = (R / RB1) * COLBLKS1;
    constexpr int NBUF1 = (NJOBS1 + NBLK - 1) / NBLK;
    constexpr int NJOBS2 = (R / RB2) * (512 / CC2);
    constexpr int NBUF2 = (NJOBS2 + NBLK - 1) / NBLK;
    static_assert(COLBLKS1 == GSIZE, "group size must match ph1 column blocks");
    static_assert(NBUF1 == NBUF2, "phases must agree on buffer count");

    // zero this block's own rows (L2-only stores; duplicated within group)
    zero_h_rows<RB1, COLBLKS1, NJOBS1>();
    {
        BarTok tk = bar_arrive();
        prestage_x<DIN, RATE, RB1, CC1, 1024, NBUF1>(xin, xs_t, xs_b, 0, smem);
        bar_wait(tk);
    }

    for (int s = 0; s < S; s++) {
        run_phase<DIN, RATE, RB1, CC1, CW1, CPT1, NBUF1, 1024, 1, 1>(
            xin, xs_t, xs_b, gkp, gb, out, os_t, os_b, s, smem);
        {
            BarTok tk = bar_arrive();
            if (PH2X == 1)
                prestage_x<DIN, RATE, RB2, CC2, 512, NBUF2>(xin, xs_t, xs_b, s, smem);
            bar_wait(tk);
        }
        run_phase<DIN, RATE, RB2, CC2, CW2, CPT2, NBUF2, 512, 2, PH2X>(
            xin, xs_t, xs_b, ckp, cb, out, os_t, os_b, s, smem);
        {
            BarTok tk = bar_arrive();
            if (s + 1 < S)
                prestage_x<DIN, RATE, RB1, CC1, 1024, NBUF1>(xin, xs_t, xs_b, s + 1, smem);
            bar_wait(tk);
        }
    }
}

// states[l][b][:] = layer-l output at time T-1
__global__ void states_kernel(const float* __restrict__ out2, float* __restrict__ st) {
    const int idx = blockIdx.x * blockDim.x + threadIdx.x;
    if (idx >= 3 * BB * HH) return;
    const int l = idx / (BB * HH);
    const int r = idx - l * (BB * HH);
    const int b = r / HH;
    const int n = r - b * HH;
    float v;
    if (l == 0)      v = g_buf0[((size_t)(TT - 1) * BB + b) * HH + n];
    else if (l == 1) v = g_buf1[((size_t)(TT - 1) * BB + b) * HH + n];
    else             v = out2[(size_t)b * TT * HH + (size_t)(TT - 1) * HH + n];
    st[idx] = v;
}

extern "C" void kernel_launch(void* const* d_in, const int* in_sizes, int n_in,
                              void* d_out, int out_size) {
    const float* x   = (const float*)d_in[0];
    const float* gk0 = (const float*)d_in[1];
    const float* gb0 = (const float*)d_in[2];
    const float* ck0 = (const float*)d_in[3];
    const float* cb0 = (const float*)d_in[4];
    const float* gk1 = (const float*)d_in[5];
    const float* gb1 = (const float*)d_in[6];
    const float* ck1 = (const float*)d_in[7];
    const float* cb1 = (const float*)d_in[8];
    const float* gk2 = (const float*)d_in[9];
    const float* gb2 = (const float*)d_in[10];
    const float* ck2 = (const float*)d_in[11];
    const float* cb2 = (const float*)d_in[12];

    float* out = (float*)d_out;
    float* st  = out + (size_t)BB * TT * HH;

    float *buf0 = nullptr, *buf1 = nullptr;
    cudaGetSymbolAddress((void**)&buf0, g_buf0);
    cudaGetSymbolAddress((void**)&buf1, g_buf1);
    float2 *gk0p, *ck0p, *gk1p, *ck1p, *gk2p, *ck2p;
    cudaGetSymbolAddress((void**)&gk0p, g_gk0p);
    cudaGetSymbolAddress((void**)&ck0p, g_ck0p);
    cudaGetSymbolAddress((void**)&gk1p, g_gk1p);
    cudaGetSymbolAddress((void**)&ck1p, g_ck1p);
    cudaGetSymbolAddress((void**)&gk2p, g_gk2p);
    cudaGetSymbolAddress((void**)&ck2p, g_ck2p);

    // One-time (per replay) weight repack into f32x2-friendly layout.
    pack_weights_kernel<<<256, 256>>>(gk0, gk0p, 768 / 2, 1024);
    pack_weights_kernel<<<256, 256>>>(ck0, ck0p, 768 / 2, 512);
    pack_weights_kernel<<<256, 256>>>(gk1, gk1p, 1024 / 2, 1024);
    pack_weights_kernel<<<256, 256>>>(ck1, ck1p, 1024 / 2, 512);
    pack_weights_kernel<<<256, 256>>>(gk2, gk2p, 1024 / 2, 1024);
    pack_weights_kernel<<<256, 256>>>(ck2, ck2p, 1024 / 2, 512);

    // Tilings (W-dup = R/RB kept under FMA time; NBUF=2 on layer 2 so both
    // jobs' x-columns prestage during barriers):
    //  k0: ph1 RB8/CC64/CPT2,  ph2 RB8/CC32/CPT1   (NBUF 1; smem 40960)
    //  k1: ph1 RB16/CC64/CPT2, ph2 RB16/CC32/CPT1  (NBUF 1; x-reuse; 98304)
    //  k2: ph1 RB16/CC64/CPT2, ph2 RB16/CC32/CPT1  (NBUF 2; smem 163840)
    auto k0 = layer_kernel<256, 1,  8, 64, 1, 2,  8, 32, 1, 1, 1>;
    auto k1 = layer_kernel<512, 2, 16, 64, 1, 2, 16, 32, 1, 1, 2>;
    auto k2 = layer_kernel<512, 4, 16, 64, 1, 2, 16, 32, 1, 1, 1>;
    cudaFuncSetAttribute(k0, cudaFuncAttributeMaxDynamicSharedMemorySize, 40960);
    cudaFuncSetAttribute(k1, cudaFuncAttributeMaxDynamicSharedMemorySize, 98304);
    cudaFuncSetAttribute(k2, cudaFuncAttributeMaxDynamicSharedMemorySize, 163840);

    // Layer 0 input: x is [B, T, 256] batch-major -> xs_t=256, xs_b=T*256.
    k0<<<NBLK, NTHR, 40960>>>(x, 256LL, (long long)TT * 256,
                              gk0p, gb0, ck0p, cb0,
                              buf0, (long long)BB * HH, (long long)HH);
    // Layers 1/2 input: time-major [T][B][512] -> xs_t=B*512, xs_b=512.
    k1<<<NBLK, NTHR, 98304>>>(buf0, (long long)BB * HH, 512LL,
                              gk1p, gb1, ck1p, cb1,
                              buf1, (long long)BB * HH, (long long)HH);
    // Final layer writes straight into d_out batch-major [B][T][512].
    k2<<<NBLK, NTHR, 163840>>>(buf1, (long long)BB * HH, 512LL,
                               gk2p, gb2, ck2p, cb2,
                               out, 512LL, (long long)TT * HH);

    if (out_size >= (int)((size_t)BB * TT * HH + 3 * BB * HH)) {
        states_kernel<<<(3 * BB * HH + 255) / 256, 256>>>(out, st);
    }
}

// round 14
// speedup vs baseline: 1.0086x; 1.0086x over previous
#include <cuda_runtime.h>
#include <math.h>

#define NBLK 128
#define NTHR 512
#define NWARPS (NTHR / 32)
#define GSIZE 16              // blocks per dependency group (== COLBLKS of ph1)
#define NGRP (NBLK / GSIZE)
#define BB 64
#define TT 512
#define HH 512

// Scratch (static __device__ arrays: allocation-free per harness rules)
__device__ float g_buf0[(size_t)TT * BB * HH];   // layer0 output, time-major [T][B][H]
__device__ float g_buf1[(size_t)TT * BB * HH];   // layer1 output, time-major
__device__ float g_h[4 * BB * HH];               // hidden state, up to R=256 rows
__device__ float g_rh[4 * BB * HH];              // r * h
__device__ float g_u[4 * BB * HH];               // update gate

// Per-group barrier cells, one 128B line each (no cross-group contention).
struct alignas(128) GBar { unsigned int cnt; unsigned int gen; unsigned int pad[30]; };
__device__ GBar g_gbar[NGRP];

// Pre-packed weights: Wp[k/2][c] = (W[k][c], W[k+1][c]) so the f32x2 FMA
// multiplier pair arrives in one LDG.64 with no packing MOVs in the hot loop.
__device__ float2 g_gk0p[(768 * 1024) / 2];
__device__ float2 g_ck0p[(768 * 512) / 2];
__device__ float2 g_gk1p[(1024 * 1024) / 2];
__device__ float2 g_ck1p[(1024 * 512) / 2];
__device__ float2 g_gk2p[(1024 * 1024) / 2];
__device__ float2 g_ck2p[(1024 * 512) / 2];

__device__ __forceinline__ unsigned long long fma2(unsigned long long a,
                                                   unsigned long long b,
                                                   unsigned long long c) {
    unsigned long long d;
    asm("fma.rn.f32x2 %0, %1, %2, %3;" : "=l"(d) : "l"(a), "l"(b), "l"(c));
    return d;
}

// Packs BOTH matrices of one layer in a single launch (3 pack launches total
// so ncu's "-s 5 -c 1" capture lands on layer kernel k2, not a pack kernel).
__global__ void pack_weights2_kernel(
    const float* __restrict__ Wg, float2* __restrict__ Wgp, int K2g, int Ng,
    const float* __restrict__ Wc, float2* __restrict__ Wcp, int K2c, int Nc) {
    const int tot_g = K2g * Ng;
    const int tot   = tot_g + K2c * Nc;
    for (int idx = blockIdx.x * blockDim.x + threadIdx.x; idx < tot;
         idx += gridDim.x * blockDim.x) {
        if (idx < tot_g) {
            const int kk2 = idx / Ng;
            const int c   = idx - kk2 * Ng;
            Wgp[idx] = make_float2(Wg[(2 * kk2) * Ng + c], Wg[(2 * kk2 + 1) * Ng + c]);
        } else {
            const int r   = idx - tot_g;
            const int kk2 = r / Nc;
            const int c   = r - kk2 * Nc;
            Wcp[r] = make_float2(Wc[(2 * kk2) * Nc + c], Wc[(2 * kk2 + 1) * Nc + c]);
        }
    }
}

// Split-phase PER-GROUP barrier (16 blocks sharing the same GRU rows) with
// scoped release/acquire — deliberately NO __threadfence(): a gpu-scope fence
// emits CCTL.IVALL on sm_103a, flushing L1. Cross-CTA mutable data
// (g_h/g_rh/g_u) is accessed L2-only (__ldcg/__stcg), so no acquire-side L1
// invalidation is ever needed. Release chain: CTA stores -> bar.sync ->
// thread-0 atom.release -> peer ld.acquire (morally strong per PTX model).
// Between bar_arrive() and bar_wait() a block may do work that reads only
// immutable inputs and writes only its own SMEM (x prestaging).
struct BarTok { unsigned int g; int last; };

__device__ __forceinline__ BarTok bar_arrive() {
    __syncthreads();
    BarTok tk; tk.g = 0; tk.last = 0;
    if (threadIdx.x == 0) {
        GBar* bar = &g_gbar[blockIdx.x / GSIZE];
        unsigned int g;
        // must read generation BEFORE arrival (else last-arriver race)
        asm volatile("ld.acquire.gpu.global.u32 %0, [%1];"
                     : "=r"(g) : "l"(&bar->gen));
        unsigned int t;
        asm volatile("atom.release.gpu.global.add.u32 %0, [%1], 1;"
                     : "=r"(t) : "l"(&bar->cnt));
        if (t == GSIZE - 1) {
            asm volatile("st.relaxed.gpu.global.u32 [%0], %1;"
                         :: "l"(&bar->cnt), "r"(0u));
            asm volatile("red.release.gpu.global.add.u32 [%0], %1;"
                         :: "l"(&bar->gen), "r"(1u));
            tk.last = 1;
        }
        tk.g = g;
    }
    return tk;
}

__device__ __forceinline__ void bar_wait(BarTok tk) {
    if (threadIdx.x == 0 && !tk.last) {
        GBar* bar = &g_gbar[blockIdx.x / GSIZE];
        unsigned int cur;
        do {
            asm volatile("ld.acquire.gpu.global.u32 %0, [%1];"
                         : "=r"(cur) : "l"(&bar->gen));
        } while (cur == tk.g);
    }
    __syncthreads();
}

__device__ __forceinline__ float sigmoidf_fast(float x) {
    return __fdividef(1.0f, 1.0f + __expf(-x));
}
// Branchless fast tanh via __expf; clamp keeps e finite (exp(30) ~ 1e13).
__device__ __forceinline__ float tanhf_fast(float x) {
    const float xc = fminf(fmaxf(x, -15.0f), 15.0f);
    const float e  = __expf(2.0f * xc);
    return __fdividef(e - 1.0f, e + 1.0f);
}

// Prestage the x-columns of ALL of this block's job tiles (NBUF operand
// buffers) into smem. Safe between bar_arrive/bar_wait: reads immutable x,
// writes own SMEM only.
template<int DIN, int RATE, int RB, int CC, int N, int NBUF>
__device__ __forceinline__ void prestage_x(
    const float* __restrict__ xin, long long xs_t, long long xs_b,
    int s, float* smem)
{
    constexpr int K = DIN + HH;
    constexpr int COLBLKS = N / CC;
    constexpr int NJOBS = (RATE * BB / RB) * COLBLKS;
    constexpr int DINV = DIN / 4;
    #pragma unroll
    for (int jb = 0; jb < NBUF; jb++) {
        const int job = blockIdx.x + jb * NBLK;
        if (job >= NJOBS) break;
        const int rowbase = (job / COLBLKS) * RB;
        float* buf = smem + jb * RB * K;
        for (int idx = threadIdx.x; idx < RB * DINV; idx += NTHR) {
            const int i = idx / DINV;
            const int k = (idx - i * DINV) * 4;
            const int j = rowbase + i;
            const int t = s * RATE + (j >> 6);
            const int b = j & 63;
            const float4 v = *reinterpret_cast<const float4*>(
                    &xin[(long long)t * xs_t + (long long)b * xs_b + k]);
            *reinterpret_cast<float4*>(&buf[i * K + k]) = v;
        }
    }
}

// Zero this block's own job rows of g_h (duplicated across the 16 blocks of
// a group — benign concurrent zero-writes, one-time cost).
template<int RB, int COLBLKS, int NJOBS>
__device__ __forceinline__ void zero_h_rows() {
    for (int job = blockIdx.x; job < NJOBS; job += NBLK) {
        const int rowbase = (job / COLBLKS) * RB;
        for (int idx = threadIdx.x; idx < RB * HH / 4; idx += NTHR)
            __stcg(reinterpret_cast<float4*>(&g_h[rowbase * HH + idx * 4]),
                   make_float4(0.f, 0.f, 0.f, 0.f));
    }
}

// One GRU phase as a tiled (R x N) = (R x K) @ (K x N) with fused epilogue.
// PHASE 1: gates (N=1024), operand = [x_t | h].   Writes g_rh (n<512), g_u.
// PHASE 2: candidate (N=512), operand = [x_t | r*h]. Writes h, out.
// Block job = RB rows x CC cols; NWARPS warps = CW column-warps x
// (NWARPS/CW) K-slices. 16 warps (4/SMSP) for scoreboard-latency hiding.
// CPT: output columns per thread (1 or 2). W-duplication over L2 = R/RB per
// step, so RB is chosen to keep LTS time under the FMA time of each phase.
// NBUF: operand buffers (== jobs per block); each job jb uses buffer jb, so
// all jobs' x-columns can be prestaged during the preceding barrier.
// XMODE: 0 = stage everything; 1 = x of ALL jobs prestaged (per-buffer);
// 2 = operand x already in buffer 0 from the previous phase (same rowblock +
// K layout; layer-1 ph2 only).
template<int DIN, int RATE, int RB, int CC, int CW, int CPT, int NBUF, int N,
         int PHASE, int XMODE>
__device__ __forceinline__ void run_phase(
    const float* __restrict__ xin, long long xs_t, long long xs_b,
    const float2* __restrict__ Wp, const float* __restrict__ bias,
    float* __restrict__ out, long long os_t, long long os_b,
    int s, float* smem)
{
    constexpr int K = DIN + HH;
    constexpr int R = RATE * BB;
    constexpr int KS = NWARPS / CW;
    constexpr int KC = K / KS;
    constexpr int ROWBLKS = R / RB;
    constexpr int COLBLKS = N / CC;
    constexpr int NJOBS = ROWBLKS * COLBLKS;
    constexpr int KV = K / 4;
    constexpr int HV = HH / 4;
    constexpr int CCV = CC / 4;
    constexpr int WCOLS = 32 * CPT;          // columns per warp
    static_assert(CW * WCOLS == CC, "warp columns must tile CC");
    static_assert(K % KS == 0 && KC % 4 == 0, "K slicing must stay aligned");
    static_assert(NJOBS <= NBUF * NBLK, "jobs must fit operand buffers");

    float* smem_red = smem + NBUF * RB * K;  // after all operand buffers

    const float* hsrc = (PHASE == 1) ? g_h : g_rh;
    const int tid  = threadIdx.x;
    const int lane = tid & 31;
    const int w    = tid >> 5;
    const int cw   = w % CW;
    const int ksid = w / CW;

    int jb = 0;
    for (int job = blockIdx.x; job < NJOBS; job += NBLK, jb++) {
        const int rb = job / COLBLKS;
        const int cb = job - rb * COLBLKS;
        const int rowbase = rb * RB;
        const int colbase = cb * CC;
        float* smem_op = smem + jb * RB * K;

        const bool skipx = (XMODE >= 1);

        // Stage operand rows [x | h-or-rh] into SMEM, float4-vectorized.
        // h/rh are cross-CTA mutable -> L2-only loads (__ldcg).
        // x is immutable within this launch -> normal cached load.
        if (skipx) {
            // x columns already in this job's buffer; stage only h/rh.
            for (int idx = tid; idx < RB * HV; idx += NTHR) {
                const int i = idx / HV;
                const int kh = (idx - i * HV) * 4;
                const int j = rowbase + i;
                const float4 v = __ldcg(reinterpret_cast<const float4*>(
                        &hsrc[j * HH + kh]));
                *reinterpret_cast<float4*>(&smem_op[i * K + DIN + kh]) = v;
            }
        } else {
            for (int idx = tid; idx < RB * KV; idx += NTHR) {
                const int i = idx / KV;
                const int k = (idx - i * KV) * 4;
                const int j = rowbase + i;
                float4 v;
                if (k < DIN) {
                    const int t = s * RATE + (j >> 6);
                    const int b = j & 63;
                    v = *reinterpret_cast<const float4*>(
                            &xin[(long long)t * xs_t + (long long)b * xs_b + k]);
                } else {
                    v = __ldcg(reinterpret_cast<const float4*>(
                            &hsrc[j * HH + (k - DIN)]));
                }
                *reinterpret_cast<float4*>(&smem_op[i * K + k]) = v;
            }
        }
        __syncthreads();

        // Packed-f32x2 dot: each lane owns CPT output columns, RB rows.
        // NOTE: W tiles (>=196KB) exceed usable L1, so W streams from L2
        // every step on every layer; RB choices keep that stream under the
        // FMA time. 4 warps/SMSP hide the LDS(29cyc)/LDG(~250-500cyc)
        // scoreboard latencies that capped the 2-warp/SMSP version.
        {
            const int c = colbase + cw * WCOLS + lane;
            const int k0 = ksid * KC;
            const unsigned long long* wq =
                reinterpret_cast<const unsigned long long*>(Wp) +
                (long long)(k0 >> 1) * N + c;
            unsigned long long acc[RB * CPT];
            #pragma unroll
            for (int i = 0; i < RB * CPT; i++) acc[i] = 0ULL;
            #pragma unroll 4
            for (int kk = 0; kk < KC; kk += 4) {
                const unsigned long long wp0 = wq[0];
                const unsigned long long wp1 = wq[N];
                unsigned long long wp2 = 0, wp3 = 0;
                if (CPT == 2) { wp2 = wq[32]; wp3 = wq[N + 32]; }
                wq += 2 * N;
                const float* sop = smem_op + k0 + kk;
                #pragma unroll
                for (int i = 0; i < RB; i++) {
                    const ulonglong2 op =
                        *reinterpret_cast<const ulonglong2*>(sop + i * K);
                    acc[i * CPT] = fma2(op.x, wp0, acc[i * CPT]);
                    acc[i * CPT] = fma2(op.y, wp1, acc[i * CPT]);
                    if (CPT == 2) {
                        acc[i * CPT + 1] = fma2(op.x, wp2, acc[i * CPT + 1]);
                        acc[i * CPT + 1] = fma2(op.y, wp3, acc[i * CPT + 1]);
                    }
                }
            }
            #pragma unroll
            for (int i = 0; i < RB; i++) {
                #pragma unroll
                for (int p = 0; p < CPT; p++) {
                    const unsigned long long a = acc[i * CPT + p];
                    const float lo = __uint_as_float((unsigned int)(a & 0xffffffffull));
                    const float hi = __uint_as_float((unsigned int)(a >> 32));
                    smem_red[(ksid * RB + i) * CC + cw * WCOLS + p * 32 + lane] =
                        lo + hi;
                }
            }
        }
        __syncthreads();

        // Reduce across K-slices + fused epilogue (float4-vectorized).
        for (int idx = tid; idx < RB * CCV; idx += NTHR) {
            const int i  = idx / CCV;
            const int cc = (idx - i * CCV) * 4;
            float4 dot = make_float4(0.f, 0.f, 0.f, 0.f);
            #pragma unroll
            for (int q = 0; q < KS; q++) {
                const float4 r = *reinterpret_cast<const float4*>(
                        &smem_red[(q * RB + i) * CC + cc]);
                dot.x += r.x; dot.y += r.y; dot.z += r.z; dot.w += r.w;
            }
            const int n = colbase + cc;
            const int j = rowbase + i;
            const float4 bv = *reinterpret_cast<const float4*>(&bias[n]);
            dot.x += bv.x; dot.y += bv.y; dot.z += bv.z; dot.w += bv.w;
            if (PHASE == 1) {
                float4 g;
                g.x = sigmoidf_fast(dot.x); g.y = sigmoidf_fast(dot.y);
                g.z = sigmoidf_fast(dot.z); g.w = sigmoidf_fast(dot.w);
                if (n < HH) {
                    const float4 hv = __ldcg(reinterpret_cast<const float4*>(
                            &g_h[j * HH + n]));
                    float4 rh;
                    rh.x = g.x * hv.x; rh.y = g.y * hv.y;
                    rh.z = g.z * hv.z; rh.w = g.w * hv.w;
                    __stcg(reinterpret_cast<float4*>(&g_rh[j * HH + n]), rh);
                } else {
                    __stcg(reinterpret_cast<float4*>(&g_u[j * HH + (n - HH)]), g);
                }
            } else {
                float4 cand;
                cand.x = tanhf_fast(dot.x); cand.y = tanhf_fast(dot.y);
                cand.z = tanhf_fast(dot.z); cand.w = tanhf_fast(dot.w);
                const float4 uu = __ldcg(reinterpret_cast<const float4*>(
                        &g_u[j * HH + n]));
                const float4 hv = __ldcg(reinterpret_cast<const float4*>(
                        &g_h[j * HH + n]));
                float4 hn;
                hn.x = uu.x * hv.x + (1.0f - uu.x) * cand.x;
                hn.y = uu.y * hv.y + (1.0f - uu.y) * cand.y;
                hn.z = uu.z * hv.z + (1.0f - uu.z) * cand.z;
                hn.w = uu.w * hv.w + (1.0f - uu.w) * cand.w;
                __stcg(reinterpret_cast<float4*>(&g_h[j * HH + n]), hn);
                const int t = s * RATE + (j >> 6);
                const int b = j & 63;
                *reinterpret_cast<float4*>(
                    &out[(long long)t * os_t + (long long)b * os_b + n]) = hn;
            }
        }
        // Trailing sync only needed if another job will reuse smem_red in
        // THIS phase; the phase-ending bar_arrive() issues its own bar.sync.
        if (job + NBLK < NJOBS) __syncthreads();
    }
}

// PH2X: XMODE for phase 2 (layer1 = 2: x reused from ph1's smem; else 1).
// Group-consistency (verified per layer): the blocks touching a given set of
// GRU rows are exactly one group of GSIZE=16 consecutive blocks, in BOTH
// phases, including layer-2's two-job mapping.
template<int DIN, int RATE,
         int RB1, int CC1, int CW1, int CPT1,
         int RB2, int CC2, int CW2, int CPT2, int PH2X>
__global__ void __launch_bounds__(NTHR, 1) layer_kernel(
    const float* __restrict__ xin, long long xs_t, long long xs_b,
    const float2* __restrict__ gkp, const float* __restrict__ gb,
    const float2* __restrict__ ckp, const float* __restrict__ cb,
    float* __restrict__ out, long long os_t, long long os_b)
{
    extern __shared__ float smem[];
    constexpr int R = RATE * BB;
    constexpr int S = TT / RATE;
    constexpr int COLBLKS1 = 1024 / CC1;
    constexpr int NJOBS1 = (R / RB1) * COLBLKS1;
    constexpr int NBUF1 = (NJOBS1 + NBLK - 1) / NBLK;
    constexpr int NJOBS2 = (R / RB2) * (512 / CC2);
    constexpr int NBUF2 = (NJOBS2 + NBLK - 1) / NBLK;
    static_assert(COLBLKS1 == GSIZE, "group size must match ph1 column blocks");
    static_assert(NBUF1 == NBUF2, "phases must agree on buffer count");

    // zero this block's own rows (L2-only stores; duplicated within group)
    zero_h_rows<RB1, COLBLKS1, NJOBS1>();
    {
        BarTok tk = bar_arrive();
        prestage_x<DIN, RATE, RB1, CC1, 1024, NBUF1>(xin, xs_t, xs_b, 0, smem);
        bar_wait(tk);
    }

    for (int s = 0; s < S; s++) {
        run_phase<DIN, RATE, RB1, CC1, CW1, CPT1, NBUF1, 1024, 1, 1>(
            xin, xs_t, xs_b, gkp, gb, out, os_t, os_b, s, smem);
        {
            BarTok tk = bar_arrive();
            if (PH2X == 1)
                prestage_x<DIN, RATE, RB2, CC2, 512, NBUF2>(xin, xs_t, xs_b, s, smem);
            bar_wait(tk);
        }
        run_phase<DIN, RATE, RB2, CC2, CW2, CPT2, NBUF2, 512, 2, PH2X>(
            xin, xs_t, xs_b, ckp, cb, out, os_t, os_b, s, smem);
        {
            BarTok tk = bar_arrive();
            if (s + 1 < S)
                prestage_x<DIN, RATE, RB1, CC1, 1024, NBUF1>(xin, xs_t, xs_b, s + 1, smem);
            bar_wait(tk);
        }
    }
}

// states[l][b][:] = layer-l output at time T-1
__global__ void states_kernel(const float* __restrict__ out2, float* __restrict__ st) {
    const int idx = blockIdx.x * blockDim.x + threadIdx.x;
    if (idx >= 3 * BB * HH) return;
    const int l = idx / (BB * HH);
    const int r = idx - l * (BB * HH);
    const int b = r / HH;
    const int n = r - b * HH;
    float v;
    if (l == 0)      v = g_buf0[((size_t)(TT - 1) * BB + b) * HH + n];
    else if (l == 1) v = g_buf1[((size_t)(TT - 1) * BB + b) * HH + n];
    else             v = out2[(size_t)b * TT * HH + (size_t)(TT - 1) * HH + n];
    st[idx] = v;
}

extern "C" void kernel_launch(void* const* d_in, const int* in_sizes, int n_in,
                              void* d_out, int out_size) {
    const float* x   = (const float*)d_in[0];
    const float* gk0 = (const float*)d_in[1];
    const float* gb0 = (const float*)d_in[2];
    const float* ck0 = (const float*)d_in[3];
    const float* cb0 = (const float*)d_in[4];
    const float* gk1 = (const float*)d_in[5];
    const float* gb1 = (const float*)d_in[6];
    const float* ck1 = (const float*)d_in[7];
    const float* cb1 = (const float*)d_in[8];
    const float* gk2 = (const float*)d_in[9];
    const float* gb2 = (const float*)d_in[10];
    const float* ck2 = (const float*)d_in[11];
    const float* cb2 = (const float*)d_in[12];

    float* out = (float*)d_out;
    float* st  = out + (size_t)BB * TT * HH;

    float *buf0 = nullptr, *buf1 = nullptr;
    cudaGetSymbolAddress((void**)&buf0, g_buf0);
    cudaGetSymbolAddress((void**)&buf1, g_buf1);
    float2 *gk0p, *ck0p, *gk1p, *ck1p, *gk2p, *ck2p;
    cudaGetSymbolAddress((void**)&gk0p, g_gk0p);
    cudaGetSymbolAddress((void**)&ck0p, g_ck0p);
    cudaGetSymbolAddress((void**)&gk1p, g_gk1p);
    cudaGetSymbolAddress((void**)&ck1p, g_ck1p);
    cudaGetSymbolAddress((void**)&gk2p, g_gk2p);
    cudaGetSymbolAddress((void**)&ck2p, g_ck2p);

    // Weight repack: 3 fused launches (one per layer) so launch index 5 is
    // k2 for ncu's "-s 5 -c 1" capture window.
    pack_weights2_kernel<<<256, 256>>>(gk0, gk0p, 768 / 2, 1024,
                                       ck0, ck0p, 768 / 2, 512);
    pack_weights2_kernel<<<256, 256>>>(gk1, gk1p, 1024 / 2, 1024,
                                       ck1, ck1p, 1024 / 2, 512);
    pack_weights2_kernel<<<256, 256>>>(gk2, gk2p, 1024 / 2, 1024,
                                       ck2, ck2p, 1024 / 2, 512);

    // Tilings unchanged from R9 (jobs 128/256; W-dup under FMA time), but
    // 512 threads (16 warps, 4/SMSP) for latency hiding. KS = 16/CW.
    //  k0: smem = op 24KB + red(ph1) 32KB = 57344
    //  k1: smem = op 64KB + red(ph1) 64KB = 131072
    //  k2: smem = op 2x64KB + red(ph1) 64KB = 196608
    auto k0 = layer_kernel<256, 1,  8, 64, 1, 2,  8, 32, 1, 1, 1>;
    auto k1 = layer_kernel<512, 2, 16, 64, 1, 2, 16, 32, 1, 1, 2>;
    auto k2 = layer_kernel<512, 4, 16, 64, 1, 2, 16, 32, 1, 1, 1>;
    cudaFuncSetAttribute(k0, cudaFuncAttributeMaxDynamicSharedMemorySize, 57344);
    cudaFuncSetAttribute(k1, cudaFuncAttributeMaxDynamicSharedMemorySize, 131072);
    cudaFuncSetAttribute(k2, cudaFuncAttributeMaxDynamicSharedMemorySize, 196608);

    // Layer 0 input: x is [B, T, 256] batch-major -> xs_t=256, xs_b=T*256.
    k0<<<NBLK, NTHR, 57344>>>(x, 256LL, (long long)TT * 256,
                              gk0p, gb0, ck0p, cb0,
                              buf0, (long long)BB * HH, (long long)HH);
    // Layers 1/2 input: time-major [T][B][512] -> xs_t=B*512, xs_b=512.
    k1<<<NBLK, NTHR, 131072>>>(buf0, (long long)BB * HH, 512LL,
                               gk1p, gb1, ck1p, cb1,
                               buf1, (long long)BB * HH, (long long)HH);
    // Final layer writes straight into d_out batch-major [B][T][512].
    k2<<<NBLK, NTHR, 196608>>>(buf1, (long long)BB * HH, 512LL,
                               gk2p, gb2, ck2p, cb2,
                               out, 512LL, (long long)TT * HH);

    if (out_size >= (int)((size_t)BB * TT * HH + 3 * BB * HH)) {
        states_kernel<<<(3 * BB * HH + 255) / 256, 256>>>(out, st);
    }
}

// round 15
// speedup vs baseline: 1.0514x; 1.0424x over previous
#include <cuda_runtime.h>
#include <math.h>

#define NBLK 128
#define NTHR 512
#define NWARPS (NTHR / 32)
#define GSIZE 16              // blocks per dependency group (== COLBLKS of ph1)
#define NGRP (NBLK / GSIZE)
#define BB 64
#define TT 512
#define HH 512

// Scratch (static __device__ arrays: allocation-free per harness rules)
__device__ float g_buf0[(size_t)TT * BB * HH];   // layer0 output, time-major [T][B][H]
__device__ float g_buf1[(size_t)TT * BB * HH];   // layer1 output, time-major
__device__ float g_h[4 * BB * HH];               // hidden state, up to R=256 rows
__device__ float g_rh[4 * BB * HH];              // r * h
__device__ float g_u[4 * BB * HH];               // update gate

// Per-group barrier cells, one 128B line each (no cross-group contention).
struct alignas(128) GBar { unsigned int cnt; unsigned int gen; unsigned int pad[30]; };
__device__ GBar g_gbar[NGRP];

// Pre-packed weights: Wp[k/2][c] = (W[k][c], W[k+1][c]) so the f32x2 FMA
// multiplier pair arrives in one LDG.64 with no packing MOVs in the hot loop.
__device__ float2 g_gk0p[(768 * 1024) / 2];
__device__ float2 g_ck0p[(768 * 512) / 2];
__device__ float2 g_gk1p[(1024 * 1024) / 2];
__device__ float2 g_ck1p[(1024 * 512) / 2];
__device__ float2 g_gk2p[(1024 * 1024) / 2];
__device__ float2 g_ck2p[(1024 * 512) / 2];

__device__ __forceinline__ unsigned long long fma2(unsigned long long a,
                                                   unsigned long long b,
                                                   unsigned long long c) {
    unsigned long long d;
    asm("fma.rn.f32x2 %0, %1, %2, %3;" : "=l"(d) : "l"(a), "l"(b), "l"(c));
    return d;
}

// Packs BOTH matrices of one layer in a single launch (3 pack launches total
// so ncu's "-s 5 -c 1" capture lands on a layer kernel, not a pack kernel).
__global__ void pack_weights2_kernel(
    const float* __restrict__ Wg, float2* __restrict__ Wgp, int K2g, int Ng,
    const float* __restrict__ Wc, float2* __restrict__ Wcp, int K2c, int Nc) {
    const int tot_g = K2g * Ng;
    const int tot   = tot_g + K2c * Nc;
    for (int idx = blockIdx.x * blockDim.x + threadIdx.x; idx < tot;
         idx += gridDim.x * blockDim.x) {
        if (idx < tot_g) {
            const int kk2 = idx / Ng;
            const int c   = idx - kk2 * Ng;
            Wgp[idx] = make_float2(Wg[(2 * kk2) * Ng + c], Wg[(2 * kk2 + 1) * Ng + c]);
        } else {
            const int r   = idx - tot_g;
            const int kk2 = r / Nc;
            const int c   = r - kk2 * Nc;
            Wcp[r] = make_float2(Wc[(2 * kk2) * Nc + c], Wc[(2 * kk2 + 1) * Nc + c]);
        }
    }
}

// Split-phase PER-GROUP barrier (16 blocks sharing the same GRU rows) with
// scoped release/acquire — deliberately NO __threadfence(): a gpu-scope fence
// emits CCTL.IVALL on sm_103a, flushing L1. Cross-CTA mutable data
// (g_h/g_rh/g_u) is accessed L2-only (__ldcg/__stcg), so no acquire-side L1
// invalidation is ever needed. Release chain: CTA stores -> bar.sync ->
// thread-0 atom.release -> peer ld.acquire (morally strong per PTX model).
// Between bar_arrive() and bar_wait() a block may do work that reads only
// immutable inputs and writes only its own SMEM (x prestaging).
struct BarTok { unsigned int g; int last; };

__device__ __forceinline__ BarTok bar_arrive() {
    __syncthreads();
    BarTok tk; tk.g = 0; tk.last = 0;
    if (threadIdx.x == 0) {
        GBar* bar = &g_gbar[blockIdx.x / GSIZE];
        unsigned int g;
        // must read generation BEFORE arrival (else last-arriver race)
        asm volatile("ld.acquire.gpu.global.u32 %0, [%1];"
                     : "=r"(g) : "l"(&bar->gen));
        unsigned int t;
        asm volatile("atom.release.gpu.global.add.u32 %0, [%1], 1;"
                     : "=r"(t) : "l"(&bar->cnt));
        if (t == GSIZE - 1) {
            asm volatile("st.relaxed.gpu.global.u32 [%0], %1;"
                         :: "l"(&bar->cnt), "r"(0u));
            asm volatile("red.release.gpu.global.add.u32 [%0], %1;"
                         :: "l"(&bar->gen), "r"(1u));
            tk.last = 1;
        }
        tk.g = g;
    }
    return tk;
}

__device__ __forceinline__ void bar_wait(BarTok tk) {
    if (threadIdx.x == 0 && !tk.last) {
        GBar* bar = &g_gbar[blockIdx.x / GSIZE];
        unsigned int cur;
        do {
            asm volatile("ld.acquire.gpu.global.u32 %0, [%1];"
                         : "=r"(cur) : "l"(&bar->gen));
        } while (cur == tk.g);
    }
    __syncthreads();
}

__device__ __forceinline__ float sigmoidf_fast(float x) {
    return __fdividef(1.0f, 1.0f + __expf(-x));
}
// Branchless fast tanh via __expf; clamp keeps e finite.
__device__ __forceinline__ float tanhf_fast(float x) {
    const float xc = fminf(fmaxf(x, -15.0f), 15.0f);
    const float e  = __expf(2.0f * xc);
    return __fdividef(e - 1.0f, e + 1.0f);
}

// Prestage the x-columns of ALL of this block's job tiles (NBUF operand
// buffers) into smem. Safe between bar_arrive/bar_wait: reads immutable x,
// writes own SMEM only.
template<int DIN, int RATE, int RB, int CC, int N, int NBUF>
__device__ __forceinline__ void prestage_x(
    const float* __restrict__ xin, long long xs_t, long long xs_b,
    int s, float* smem)
{
    constexpr int K = DIN + HH;
    constexpr int COLBLKS = N / CC;
    constexpr int NJOBS = (RATE * BB / RB) * COLBLKS;
    constexpr int DINV = DIN / 4;
    #pragma unroll
    for (int jb = 0; jb < NBUF; jb++) {
        const int job = blockIdx.x + jb * NBLK;
        if (job >= NJOBS) break;
        const int rowbase = (job / COLBLKS) * RB;
        float* buf = smem + jb * RB * K;
        for (int idx = threadIdx.x; idx < RB * DINV; idx += NTHR) {
            const int i = idx / DINV;
            const int k = (idx - i * DINV) * 4;
            const int j = rowbase + i;
            const int t = s * RATE + (j >> 6);
            const int b = j & 63;
            const float4 v = *reinterpret_cast<const float4*>(
                    &xin[(long long)t * xs_t + (long long)b * xs_b + k]);
            *reinterpret_cast<float4*>(&buf[i * K + k]) = v;
        }
    }
}

// Zero this block's own job rows of g_h (duplicated across the 16 blocks of
// a group — benign concurrent zero-writes, one-time cost).
template<int RB, int COLBLKS, int NJOBS>
__device__ __forceinline__ void zero_h_rows() {
    for (int job = blockIdx.x; job < NJOBS; job += NBLK) {
        const int rowbase = (job / COLBLKS) * RB;
        for (int idx = threadIdx.x; idx < RB * HH / 4; idx += NTHR)
            __stcg(reinterpret_cast<float4*>(&g_h[rowbase * HH + idx * 4]),
                   make_float4(0.f, 0.f, 0.f, 0.f));
    }
}

// One GRU phase as a tiled (R x N) = (R x K) @ (K x N) with fused epilogue.
// PHASE 1: gates (N=1024), operand = [x_t | h].   Writes g_rh (n<512), g_u.
// PHASE 2: candidate (N=512), operand = [x_t | r*h]. Writes h, out.
// The dot uses a DISTANCE-2 software pipeline on the W loads (regs a*/b*),
// guaranteeing MLP=2 on the L2 W-stream even at the 128-reg/thread cap —
// the R14 profile (fma 18.6%, issue 22.5%, nothing saturated) showed the
// un-pipelined W-load latency chain was the binder.
template<int DIN, int RATE, int RB, int CC, int CW, int CPT, int NBUF, int N,
         int PHASE, int XMODE>
__device__ __forceinline__ void run_phase(
    const float* __restrict__ xin, long long xs_t, long long xs_b,
    const float2* __restrict__ Wp, const float* __restrict__ bias,
    float* __restrict__ out, long long os_t, long long os_b,
    int s, float* smem)
{
    constexpr int K = DIN + HH;
    constexpr int R = RATE * BB;
    constexpr int KS = NWARPS / CW;
    constexpr int KC = K / KS;
    constexpr int ROWBLKS = R / RB;
    constexpr int COLBLKS = N / CC;
    constexpr int NJOBS = ROWBLKS * COLBLKS;
    constexpr int KV = K / 4;
    constexpr int HV = HH / 4;
    constexpr int CCV = CC / 4;
    constexpr int WCOLS = 32 * CPT;          // columns per warp
    constexpr int NG = KC / 4;               // 4-k groups per K-slice
    static_assert(CW * WCOLS == CC, "warp columns must tile CC");
    static_assert(K % KS == 0 && KC % 4 == 0, "K slicing must stay aligned");
    static_assert(NJOBS <= NBUF * NBLK, "jobs must fit operand buffers");
    static_assert(NG >= 3, "pipeline needs >=3 groups");

    float* smem_red = smem + NBUF * RB * K;  // after all operand buffers

    const float* hsrc = (PHASE == 1) ? g_h : g_rh;
    const int tid  = threadIdx.x;
    const int lane = tid & 31;
    const int w    = tid >> 5;
    const int cw   = w % CW;
    const int ksid = w / CW;

    int jb = 0;
    for (int job = blockIdx.x; job < NJOBS; job += NBLK, jb++) {
        const int rb = job / COLBLKS;
        const int cb = job - rb * COLBLKS;
        const int rowbase = rb * RB;
        const int colbase = cb * CC;
        float* smem_op = smem + jb * RB * K;

        const bool skipx = (XMODE >= 1);

        // Stage operand rows [x | h-or-rh] into SMEM, float4-vectorized.
        // h/rh are cross-CTA mutable -> L2-only loads (__ldcg).
        // x is immutable within this launch -> normal cached load.
        if (skipx) {
            // x columns already in this job's buffer; stage only h/rh.
            for (int idx = tid; idx < RB * HV; idx += NTHR) {
                const int i = idx / HV;
                const int kh = (idx - i * HV) * 4;
                const int j = rowbase + i;
                const float4 v = __ldcg(reinterpret_cast<const float4*>(
                        &hsrc[j * HH + kh]));
                *reinterpret_cast<float4*>(&smem_op[i * K + DIN + kh]) = v;
            }
        } else {
            for (int idx = tid; idx < RB * KV; idx += NTHR) {
                const int i = idx / KV;
                const int k = (idx - i * KV) * 4;
                const int j = rowbase + i;
                float4 v;
                if (k < DIN) {
                    const int t = s * RATE + (j >> 6);
                    const int b = j & 63;
                    v = *reinterpret_cast<const float4*>(
                            &xin[(long long)t * xs_t + (long long)b * xs_b + k]);
                } else {
                    v = __ldcg(reinterpret_cast<const float4*>(
                            &hsrc[j * HH + (k - DIN)]));
                }
                *reinterpret_cast<float4*>(&smem_op[i * K + k]) = v;
            }
        }
        __syncthreads();

        // Packed-f32x2 dot, distance-2 W-load pipeline.
        {
            const int c = colbase + cw * WCOLS + lane;
            const int k0 = ksid * KC;
            const unsigned long long* wq =
                reinterpret_cast<const unsigned long long*>(Wp) +
                (long long)(k0 >> 1) * N + c;
            unsigned long long acc[RB * CPT];
            #pragma unroll
            for (int i = 0; i < RB * CPT; i++) acc[i] = 0ULL;

            // prologue: groups 0 and 1 in flight
            unsigned long long a0 = wq[0], a1 = wq[N];
            unsigned long long a2 = 0, a3 = 0;
            if (CPT == 2) { a2 = wq[32]; a3 = wq[N + 32]; }
            wq += 2 * N;
            unsigned long long b0 = wq[0], b1 = wq[N];
            unsigned long long b2 = 0, b3 = 0;
            if (CPT == 2) { b2 = wq[32]; b3 = wq[N + 32]; }
            wq += 2 * N;

            #pragma unroll
            for (int g = 0; g < NG; g++) {
                const unsigned long long wp0 = a0, wp1 = a1;
                const unsigned long long wp2 = a2, wp3 = a3;
                a0 = b0; a1 = b1; a2 = b2; a3 = b3;
                if (g + 2 < NG) {
                    b0 = wq[0]; b1 = wq[N];
                    if (CPT == 2) { b2 = wq[32]; b3 = wq[N + 32]; }
                    wq += 2 * N;
                }
                const float* sop = smem_op + k0 + g * 4;
                #pragma unroll
                for (int i = 0; i < RB; i++) {
                    const ulonglong2 op =
                        *reinterpret_cast<const ulonglong2*>(sop + i * K);
                    acc[i * CPT] = fma2(op.x, wp0, acc[i * CPT]);
                    acc[i * CPT] = fma2(op.y, wp1, acc[i * CPT]);
                    if (CPT == 2) {
                        acc[i * CPT + 1] = fma2(op.x, wp2, acc[i * CPT + 1]);
                        acc[i * CPT + 1] = fma2(op.y, wp3, acc[i * CPT + 1]);
                    }
                }
            }
            #pragma unroll
            for (int i = 0; i < RB; i++) {
                #pragma unroll
                for (int p = 0; p < CPT; p++) {
                    const unsigned long long a = acc[i * CPT + p];
                    const float lo = __uint_as_float((unsigned int)(a & 0xffffffffull));
                    const float hi = __uint_as_float((unsigned int)(a >> 32));
                    smem_red[(ksid * RB + i) * CC + cw * WCOLS + p * 32 + lane] =
                        lo + hi;
                }
            }
        }
        __syncthreads();

        // Reduce across K-slices + fused epilogue (float4-vectorized).
        for (int idx = tid; idx < RB * CCV; idx += NTHR) {
            const int i  = idx / CCV;
            const int cc = (idx - i * CCV) * 4;
            float4 dot = make_float4(0.f, 0.f, 0.f, 0.f);
            #pragma unroll
            for (int q = 0; q < KS; q++) {
                const float4 r = *reinterpret_cast<const float4*>(
                        &smem_red[(q * RB + i) * CC + cc]);
                dot.x += r.x; dot.y += r.y; dot.z += r.z; dot.w += r.w;
            }
            const int n = colbase + cc;
            const int j = rowbase + i;
            const float4 bv = *reinterpret_cast<const float4*>(&bias[n]);
            dot.x += bv.x; dot.y += bv.y; dot.z += bv.z; dot.w += bv.w;
            if (PHASE == 1) {
                float4 g;
                g.x = sigmoidf_fast(dot.x); g.y = sigmoidf_fast(dot.y);
                g.z = sigmoidf_fast(dot.z); g.w = sigmoidf_fast(dot.w);
                if (n < HH) {
                    const float4 hv = __ldcg(reinterpret_cast<const float4*>(
                            &g_h[j * HH + n]));
                    float4 rh;
                    rh.x = g.x * hv.x; rh.y = g.y * hv.y;
                    rh.z = g.z * hv.z; rh.w = g.w * hv.w;
                    __stcg(reinterpret_cast<float4*>(&g_rh[j * HH + n]), rh);
                } else {
                    __stcg(reinterpret_cast<float4*>(&g_u[j * HH + (n - HH)]), g);
                }
            } else {
                float4 cand;
                cand.x = tanhf_fast(dot.x); cand.y = tanhf_fast(dot.y);
                cand.z = tanhf_fast(dot.z); cand.w = tanhf_fast(dot.w);
                const float4 uu = __ldcg(reinterpret_cast<const float4*>(
                        &g_u[j * HH + n]));
                const float4 hv = __ldcg(reinterpret_cast<const float4*>(
                        &g_h[j * HH + n]));
                float4 hn;
                hn.x = uu.x * hv.x + (1.0f - uu.x) * cand.x;
                hn.y = uu.y * hv.y + (1.0f - uu.y) * cand.y;
                hn.z = uu.z * hv.z + (1.0f - uu.z) * cand.z;
                hn.w = uu.w * hv.w + (1.0f - uu.w) * cand.w;
                __stcg(reinterpret_cast<float4*>(&g_h[j * HH + n]), hn);
                const int t = s * RATE + (j >> 6);
                const int b = j & 63;
                *reinterpret_cast<float4*>(
                    &out[(long long)t * os_t + (long long)b * os_b + n]) = hn;
            }
        }
        // Trailing sync only needed if another job will reuse smem_red in
        // THIS phase; the phase-ending bar_arrive() issues its own bar.sync.
        if (job + NBLK < NJOBS) __syncthreads();
    }
}

// PH2X: XMODE for phase 2 (layer1 = 2: x reused from ph1's smem; else 1).
// Group-consistency (verified per layer): the blocks touching a given set of
// GRU rows are exactly one group of GSIZE=16 consecutive blocks, in BOTH
// phases, including layer-2's two-job mapping.
template<int DIN, int RATE,
         int RB1, int CC1, int CW1, int CPT1,
         int RB2, int CC2, int CW2, int CPT2, int PH2X>
__global__ void __launch_bounds__(NTHR, 1) layer_kernel(
    const float* __restrict__ xin, long long xs_t, long long xs_b,
    const float2* __restrict__ gkp, const float* __restrict__ gb,
    const float2* __restrict__ ckp, const float* __restrict__ cb,
    float* __restrict__ out, long long os_t, long long os_b)
{
    extern __shared__ float smem[];
    constexpr int R = RATE * BB;
    constexpr int S = TT / RATE;
    constexpr int COLBLKS1 = 1024 / CC1;
    constexpr int NJOBS1 = (R / RB1) * COLBLKS1;
    constexpr int NBUF1 = (NJOBS1 + NBLK - 1) / NBLK;
    constexpr int NJOBS2 = (R / RB2) * (512 / CC2);
    constexpr int NBUF2 = (NJOBS2 + NBLK - 1) / NBLK;
    static_assert(COLBLKS1 == GSIZE, "group size must match ph1 column blocks");
    static_assert(NBUF1 == NBUF2, "phases must agree on buffer count");

    // zero this block's own rows (L2-only stores; duplicated within group)
    zero_h_rows<RB1, COLBLKS1, NJOBS1>();
    {
        BarTok tk = bar_arrive();
        prestage_x<DIN, RATE, RB1, CC1, 1024, NBUF1>(xin, xs_t, xs_b, 0, smem);
        bar_wait(tk);
    }

    for (int s = 0; s < S; s++) {
        run_phase<DIN, RATE, RB1, CC1, CW1, CPT1, NBUF1, 1024, 1, 1>(
            xin, xs_t, xs_b, gkp, gb, out, os_t, os_b, s, smem);
        {
            BarTok tk = bar_arrive();
            if (PH2X == 1)
                prestage_x<DIN, RATE, RB2, CC2, 512, NBUF2>(xin, xs_t, xs_b, s, smem);
            bar_wait(tk);
        }
        run_phase<DIN, RATE, RB2, CC2, CW2, CPT2, NBUF2, 512, 2, PH2X>(
            xin, xs_t, xs_b, ckp, cb, out, os_t, os_b, s, smem);
        {
            BarTok tk = bar_arrive();
            if (s + 1 < S)
                prestage_x<DIN, RATE, RB1, CC1, 1024, NBUF1>(xin, xs_t, xs_b, s + 1, smem);
            bar_wait(tk);
        }
    }
}

// states[l][b][:] = layer-l output at time T-1
__global__ void states_kernel(const float* __restrict__ out2, float* __restrict__ st) {
    const int idx = blockIdx.x * blockDim.x + threadIdx.x;
    if (idx >= 3 * BB * HH) return;
    const int l = idx / (BB * HH);
    const int r = idx - l * (BB * HH);
    const int b = r / HH;
    const int n = r - b * HH;
    float v;
    if (l == 0)      v = g_buf0[((size_t)(TT - 1) * BB + b) * HH + n];
    else if (l == 1) v = g_buf1[((size_t)(TT - 1) * BB + b) * HH + n];
    else             v = out2[(size_t)b * TT * HH + (size_t)(TT - 1) * HH + n];
    st[idx] = v;
}

extern "C" void kernel_launch(void* const* d_in, const int* in_sizes, int n_in,
                              void* d_out, int out_size) {
    const float* x   = (const float*)d_in[0];
    const float* gk0 = (const float*)d_in[1];
    const float* gb0 = (const float*)d_in[2];
    const float* ck0 = (const float*)d_in[3];
    const float* cb0 = (const float*)d_in[4];
    const float* gk1 = (const float*)d_in[5];
    const float* gb1 = (const float*)d_in[6];
    const float* ck1 = (const float*)d_in[7];
    const float* cb1 = (const float*)d_in[8];
    const float* gk2 = (const float*)d_in[9];
    const float* gb2 = (const float*)d_in[10];
    const float* ck2 = (const float*)d_in[11];
    const float* cb2 = (const float*)d_in[12];

    float* out = (float*)d_out;
    float* st  = out + (size_t)BB * TT * HH;

    float *buf0 = nullptr, *buf1 = nullptr;
    cudaGetSymbolAddress((void**)&buf0, g_buf0);
    cudaGetSymbolAddress((void**)&buf1, g_buf1);
    float2 *gk0p, *ck0p, *gk1p, *ck1p, *gk2p, *ck2p;
    cudaGetSymbolAddress((void**)&gk0p, g_gk0p);
    cudaGetSymbolAddress((void**)&ck0p, g_ck0p);
    cudaGetSymbolAddress((void**)&gk1p, g_gk1p);
    cudaGetSymbolAddress((void**)&ck1p, g_ck1p);
    cudaGetSymbolAddress((void**)&gk2p, g_gk2p);
    cudaGetSymbolAddress((void**)&ck2p, g_ck2p);

    // Weight repack: 3 fused launches (one per layer) so launch index 5 is
    // a layer kernel for ncu's "-s 5 -c 1" capture window.
    pack_weights2_kernel<<<256, 256>>>(gk0, gk0p, 768 / 2, 1024,
                                       ck0, ck0p, 768 / 2, 512);
    pack_weights2_kernel<<<256, 256>>>(gk1, gk1p, 1024 / 2, 1024,
                                       ck1, ck1p, 1024 / 2, 512);
    pack_weights2_kernel<<<256, 256>>>(gk2, gk2p, 1024 / 2, 1024,
                                       ck2, ck2p, 1024 / 2, 512);

    // Tilings unchanged from R14 (only the dot loop gained the distance-2
    // W-load pipeline, so the delta is attributable to that one change).
    auto k0 = layer_kernel<256, 1,  8, 64, 1, 2,  8, 32, 1, 1, 1>;
    auto k1 = layer_kernel<512, 2, 16, 64, 1, 2, 16, 32, 1, 1, 2>;
    auto k2 = layer_kernel<512, 4, 16, 64, 1, 2, 16, 32, 1, 1, 1>;
    cudaFuncSetAttribute(k0, cudaFuncAttributeMaxDynamicSharedMemorySize, 57344);
    cudaFuncSetAttribute(k1, cudaFuncAttributeMaxDynamicSharedMemorySize, 131072);
    cudaFuncSetAttribute(k2, cudaFuncAttributeMaxDynamicSharedMemorySize, 196608);

    // Layer 0 input: x is [B, T, 256] batch-major -> xs_t=256, xs_b=T*256.
    k0<<<NBLK, NTHR, 57344>>>(x, 256LL, (long long)TT * 256,
                              gk0p, gb0, ck0p, cb0,
                              buf0, (long long)BB * HH, (long long)HH);
    // Layers 1/2 input: time-major [T][B][512] -> xs_t=B*512, xs_b=512.
    k1<<<NBLK, NTHR, 131072>>>(buf0, (long long)BB * HH, 512LL,
                               gk1p, gb1, ck1p, cb1,
                               buf1, (long long)BB * HH, (long long)HH);
    // Final layer writes straight into d_out batch-major [B][T][512].
    k2<<<NBLK, NTHR, 196608>>>(buf1, (long long)BB * HH, 512LL,
                               gk2p, gb2, ck2p, cb2,
                               out, 512LL, (long long)TT * HH);

    if (out_size >= (int)((size_t)BB * TT * HH + 3 * BB * HH)) {
        states_kernel<<<(3 * BB * HH + 255) / 256, 256>>>(out, st);
    }
}

// round 16
// speedup vs baseline: 1.1635x; 1.1067x over previous
#include <cuda_runtime.h>
#include <math.h>

#define NBLK 256
#define NTHR 256
#define NWARPS (NTHR / 32)
#define GSIZE 16              // blocks per dependency group (== COLBLKS of ph1)
#define NGRP (NBLK / GSIZE)
#define BB 64
#define TT 512
#define HH 512

// Scratch (static __device__ arrays: allocation-free per harness rules)
__device__ float g_buf0[(size_t)TT * BB * HH];   // layer0 output, time-major [T][B][H]
__device__ float g_buf1[(size_t)TT * BB * HH];   // layer1 output, time-major
__device__ float g_h[4 * BB * HH];               // hidden state, up to R=256 rows
__device__ float g_rh[4 * BB * HH];              // r * h
__device__ float g_u[4 * BB * HH];               // update gate

// Per-group barrier cells, one 128B line each (no cross-group contention).
struct alignas(128) GBar { unsigned int cnt; unsigned int gen; unsigned int pad[30]; };
__device__ GBar g_gbar[NGRP];

// Pre-packed weights: Wp[k/2][c] = (W[k][c], W[k+1][c]) so the f32x2 FMA
// multiplier pair arrives in one LDG.64 with no packing MOVs in the hot loop.
__device__ float2 g_gk0p[(768 * 1024) / 2];
__device__ float2 g_ck0p[(768 * 512) / 2];
__device__ float2 g_gk1p[(1024 * 1024) / 2];
__device__ float2 g_ck1p[(1024 * 512) / 2];
__device__ float2 g_gk2p[(1024 * 1024) / 2];
__device__ float2 g_ck2p[(1024 * 512) / 2];

__device__ __forceinline__ unsigned long long fma2(unsigned long long a,
                                                   unsigned long long b,
                                                   unsigned long long c) {
    unsigned long long d;
    asm("fma.rn.f32x2 %0, %1, %2, %3;" : "=l"(d) : "l"(a), "l"(b), "l"(c));
    return d;
}

// Packs BOTH matrices of one layer in a single launch (3 pack launches total
// so ncu's "-s 5 -c 1" capture lands on a layer kernel, not a pack kernel).
__global__ void pack_weights2_kernel(
    const float* __restrict__ Wg, float2* __restrict__ Wgp, int K2g, int Ng,
    const float* __restrict__ Wc, float2* __restrict__ Wcp, int K2c, int Nc) {
    const int tot_g = K2g * Ng;
    const int tot   = tot_g + K2c * Nc;
    for (int idx = blockIdx.x * blockDim.x + threadIdx.x; idx < tot;
         idx += gridDim.x * blockDim.x) {
        if (idx < tot_g) {
            const int kk2 = idx / Ng;
            const int c   = idx - kk2 * Ng;
            Wgp[idx] = make_float2(Wg[(2 * kk2) * Ng + c], Wg[(2 * kk2 + 1) * Ng + c]);
        } else {
            const int r   = idx - tot_g;
            const int kk2 = r / Nc;
            const int c   = r - kk2 * Nc;
            Wcp[r] = make_float2(Wc[(2 * kk2) * Nc + c], Wc[(2 * kk2 + 1) * Nc + c]);
        }
    }
}

// Split-phase PER-GROUP barrier (16 blocks sharing the same GRU rows) with
// scoped release/acquire — deliberately NO __threadfence() (IVALL would
// flush L1). Cross-CTA mutable data (g_h/g_rh/g_u) is L2-only (__ldcg/__stcg).
// With 2 CTAs/SM, when one group's block waits here, the co-resident block
// of an INDEPENDENT group keeps the SM busy — this cross-group overlap is
// the point of the R16 restructure (per-phase serial chain was the binder).
struct BarTok { unsigned int g; int last; };

__device__ __forceinline__ BarTok bar_arrive() {
    __syncthreads();
    BarTok tk; tk.g = 0; tk.last = 0;
    if (threadIdx.x == 0) {
        GBar* bar = &g_gbar[blockIdx.x / GSIZE];
        unsigned int g;
        // must read generation BEFORE arrival (else last-arriver race)
        asm volatile("ld.acquire.gpu.global.u32 %0, [%1];"
                     : "=r"(g) : "l"(&bar->gen));
        unsigned int t;
        asm volatile("atom.release.gpu.global.add.u32 %0, [%1], 1;"
                     : "=r"(t) : "l"(&bar->cnt));
        if (t == GSIZE - 1) {
            asm volatile("st.relaxed.gpu.global.u32 [%0], %1;"
                         :: "l"(&bar->cnt), "r"(0u));
            asm volatile("red.release.gpu.global.add.u32 [%0], %1;"
                         :: "l"(&bar->gen), "r"(1u));
            tk.last = 1;
        }
        tk.g = g;
    }
    return tk;
}

__device__ __forceinline__ void bar_wait(BarTok tk) {
    if (threadIdx.x == 0 && !tk.last) {
        GBar* bar = &g_gbar[blockIdx.x / GSIZE];
        unsigned int cur;
        do {
            asm volatile("ld.acquire.gpu.global.u32 %0, [%1];"
                         : "=r"(cur) : "l"(&bar->gen));
        } while (cur == tk.g);
    }
    __syncthreads();
}

__device__ __forceinline__ float sigmoidf_fast(float x) {
    return __fdividef(1.0f, 1.0f + __expf(-x));
}
// Branchless fast tanh via __expf; clamp keeps e finite.
__device__ __forceinline__ float tanhf_fast(float x) {
    const float xc = fminf(fmaxf(x, -15.0f), 15.0f);
    const float e  = __expf(2.0f * xc);
    return __fdividef(e - 1.0f, e + 1.0f);
}

// Prestage the x-columns of this block's (single) job tile into smem.
// Safe between bar_arrive/bar_wait: reads immutable x, writes own SMEM only.
template<int DIN, int RATE, int RB, int CC, int N>
__device__ __forceinline__ void prestage_x(
    const float* __restrict__ xin, long long xs_t, long long xs_b,
    int s, float* smem)
{
    constexpr int K = DIN + HH;
    constexpr int COLBLKS = N / CC;
    constexpr int DINV = DIN / 4;
    const int rowbase = ((int)blockIdx.x / COLBLKS) * RB;
    for (int idx = threadIdx.x; idx < RB * DINV; idx += NTHR) {
        const int i = idx / DINV;
        const int k = (idx - i * DINV) * 4;
        const int j = rowbase + i;
        const int t = s * RATE + (j >> 6);
        const int b = j & 63;
        const float4 v = *reinterpret_cast<const float4*>(
                &xin[(long long)t * xs_t + (long long)b * xs_b + k]);
        *reinterpret_cast<float4*>(&smem[i * K + k]) = v;
    }
}

// Zero this block's own job rows of g_h (duplicated within group — benign).
template<int RB, int COLBLKS, int NJOBS>
__device__ __forceinline__ void zero_h_rows() {
    for (int job = blockIdx.x; job < NJOBS; job += NBLK) {
        const int rowbase = (job / COLBLKS) * RB;
        for (int idx = threadIdx.x; idx < RB * HH / 4; idx += NTHR)
            __stcg(reinterpret_cast<float4*>(&g_h[rowbase * HH + idx * 4]),
                   make_float4(0.f, 0.f, 0.f, 0.f));
    }
}

// One GRU phase as a tiled (R x N) = (R x K) @ (K x N) with fused epilogue.
// PHASE 1: gates (N=1024), operand = [x_t | h].   Writes g_rh (n<512), g_u.
// PHASE 2: candidate (N=512), operand = [x_t | r*h]. Writes h, out.
// Exactly ONE job per block now (NJOBS == NBLK for every phase/layer).
// Distance-2 W-load software pipeline retained from R15 (small win).
template<int DIN, int RATE, int RB, int CC, int CW, int CPT, int N,
         int PHASE, int XMODE>
__device__ __forceinline__ void run_phase(
    const float* __restrict__ xin, long long xs_t, long long xs_b,
    const float2* __restrict__ Wp, const float* __restrict__ bias,
    float* __restrict__ out, long long os_t, long long os_b,
    int s, float* smem)
{
    constexpr int K = DIN + HH;
    constexpr int R = RATE * BB;
    constexpr int KS = NWARPS / CW;
    constexpr int KC = K / KS;
    constexpr int ROWBLKS = R / RB;
    constexpr int COLBLKS = N / CC;
    constexpr int NJOBS = ROWBLKS * COLBLKS;
    constexpr int KV = K / 4;
    constexpr int HV = HH / 4;
    constexpr int CCV = CC / 4;
    constexpr int WCOLS = 32 * CPT;          // columns per warp
    constexpr int NG = KC / 4;               // 4-k groups per K-slice
    static_assert(CW * WCOLS == CC, "warp columns must tile CC");
    static_assert(K % KS == 0 && KC % 4 == 0, "K slicing must stay aligned");
    static_assert(NJOBS == NBLK, "one job per block");
    static_assert(NG >= 3, "pipeline needs >=3 groups");

    float* smem_op  = smem;
    float* smem_red = smem + RB * K;

    const float* hsrc = (PHASE == 1) ? g_h : g_rh;
    const int tid  = threadIdx.x;
    const int lane = tid & 31;
    const int w    = tid >> 5;
    const int cw   = w % CW;
    const int ksid = w / CW;

    const int job = blockIdx.x;
    const int rb = job / COLBLKS;
    const int cb = job - rb * COLBLKS;
    const int rowbase = rb * RB;
    const int colbase = cb * CC;

    // Stage operand rows [x | h-or-rh] into SMEM, float4-vectorized.
    // h/rh are cross-CTA mutable -> L2-only loads (__ldcg).
    if (XMODE >= 1) {
        // x columns already in smem; stage only h/rh.
        for (int idx = tid; idx < RB * HV; idx += NTHR) {
            const int i = idx / HV;
            const int kh = (idx - i * HV) * 4;
            const int j = rowbase + i;
            const float4 v = __ldcg(reinterpret_cast<const float4*>(
                    &hsrc[j * HH + kh]));
            *reinterpret_cast<float4*>(&smem_op[i * K + DIN + kh]) = v;
        }
    } else {
        for (int idx = tid; idx < RB * KV; idx += NTHR) {
            const int i = idx / KV;
            const int k = (idx - i * KV) * 4;
            const int j = rowbase + i;
            float4 v;
            if (k < DIN) {
                const int t = s * RATE + (j >> 6);
                const int b = j & 63;
                v = *reinterpret_cast<const float4*>(
                        &xin[(long long)t * xs_t + (long long)b * xs_b + k]);
            } else {
                v = __ldcg(reinterpret_cast<const float4*>(
                        &hsrc[j * HH + (k - DIN)]));
            }
            *reinterpret_cast<float4*>(&smem_op[i * K + k]) = v;
        }
    }
    __syncthreads();

    // Packed-f32x2 dot, distance-2 W-load pipeline.
    {
        const int c = colbase + cw * WCOLS + lane;
        const int k0 = ksid * KC;
        const unsigned long long* wq =
            reinterpret_cast<const unsigned long long*>(Wp) +
            (long long)(k0 >> 1) * N + c;
        unsigned long long acc[RB * CPT];
        #pragma unroll
        for (int i = 0; i < RB * CPT; i++) acc[i] = 0ULL;

        unsigned long long a0 = wq[0], a1 = wq[N];
        unsigned long long a2 = 0, a3 = 0;
        if (CPT == 2) { a2 = wq[32]; a3 = wq[N + 32]; }
        wq += 2 * N;
        unsigned long long b0 = wq[0], b1 = wq[N];
        unsigned long long b2 = 0, b3 = 0;
        if (CPT == 2) { b2 = wq[32]; b3 = wq[N + 32]; }
        wq += 2 * N;

        #pragma unroll
        for (int g = 0; g < NG; g++) {
            const unsigned long long wp0 = a0, wp1 = a1;
            const unsigned long long wp2 = a2, wp3 = a3;
            a0 = b0; a1 = b1; a2 = b2; a3 = b3;
            if (g + 2 < NG) {
                b0 = wq[0]; b1 = wq[N];
                if (CPT == 2) { b2 = wq[32]; b3 = wq[N + 32]; }
                wq += 2 * N;
            }
            const float* sop = smem_op + k0 + g * 4;
            #pragma unroll
            for (int i = 0; i < RB; i++) {
                const ulonglong2 op =
                    *reinterpret_cast<const ulonglong2*>(sop + i * K);
                acc[i * CPT] = fma2(op.x, wp0, acc[i * CPT]);
                acc[i * CPT] = fma2(op.y, wp1, acc[i * CPT]);
                if (CPT == 2) {
                    acc[i * CPT + 1] = fma2(op.x, wp2, acc[i * CPT + 1]);
                    acc[i * CPT + 1] = fma2(op.y, wp3, acc[i * CPT + 1]);
                }
            }
        }
        #pragma unroll
        for (int i = 0; i < RB; i++) {
            #pragma unroll
            for (int p = 0; p < CPT; p++) {
                const unsigned long long a = acc[i * CPT + p];
                const float lo = __uint_as_float((unsigned int)(a & 0xffffffffull));
                const float hi = __uint_as_float((unsigned int)(a >> 32));
                smem_red[(ksid * RB + i) * CC + cw * WCOLS + p * 32 + lane] =
                    lo + hi;
            }
        }
    }
    __syncthreads();

    // Reduce across K-slices + fused epilogue (float4-vectorized).
    for (int idx = tid; idx < RB * CCV; idx += NTHR) {
        const int i  = idx / CCV;
        const int cc = (idx - i * CCV) * 4;
        float4 dot = make_float4(0.f, 0.f, 0.f, 0.f);
        #pragma unroll
        for (int q = 0; q < KS; q++) {
            const float4 r = *reinterpret_cast<const float4*>(
                    &smem_red[(q * RB + i) * CC + cc]);
            dot.x += r.x; dot.y += r.y; dot.z += r.z; dot.w += r.w;
        }
        const int n = colbase + cc;
        const int j = rowbase + i;
        const float4 bv = *reinterpret_cast<const float4*>(&bias[n]);
        dot.x += bv.x; dot.y += bv.y; dot.z += bv.z; dot.w += bv.w;
        if (PHASE == 1) {
            float4 g;
            g.x = sigmoidf_fast(dot.x); g.y = sigmoidf_fast(dot.y);
            g.z = sigmoidf_fast(dot.z); g.w = sigmoidf_fast(dot.w);
            if (n < HH) {
                const float4 hv = __ldcg(reinterpret_cast<const float4*>(
                        &g_h[j * HH + n]));
                float4 rh;
                rh.x = g.x * hv.x; rh.y = g.y * hv.y;
                rh.z = g.z * hv.z; rh.w = g.w * hv.w;
                __stcg(reinterpret_cast<float4*>(&g_rh[j * HH + n]), rh);
            } else {
                __stcg(reinterpret_cast<float4*>(&g_u[j * HH + (n - HH)]), g);
            }
        } else {
            float4 cand;
            cand.x = tanhf_fast(dot.x); cand.y = tanhf_fast(dot.y);
            cand.z = tanhf_fast(dot.z); cand.w = tanhf_fast(dot.w);
            const float4 uu = __ldcg(reinterpret_cast<const float4*>(
                    &g_u[j * HH + n]));
            const float4 hv = __ldcg(reinterpret_cast<const float4*>(
                    &g_h[j * HH + n]));
            float4 hn;
            hn.x = uu.x * hv.x + (1.0f - uu.x) * cand.x;
            hn.y = uu.y * hv.y + (1.0f - uu.y) * cand.y;
            hn.z = uu.z * hv.z + (1.0f - uu.z) * cand.z;
            hn.w = uu.w * hv.w + (1.0f - uu.w) * cand.w;
            __stcg(reinterpret_cast<float4*>(&g_h[j * HH + n]), hn);
            const int t = s * RATE + (j >> 6);
            const int b = j & 63;
            *reinterpret_cast<float4*>(
                &out[(long long)t * os_t + (long long)b * os_b + n]) = hn;
        }
    }
    // No trailing sync: one job per block; bar_arrive() begins with bar.sync.
}

// PH2X: XMODE for phase 2 (layer1 = 2: x reused from ph1's smem; else 1).
// Group-consistency: with ph2's COLBLKS == 16 == ph1's and identical RB per
// layer, blocks b and their rowbases match across phases; each group of 16
// consecutive blocks owns the same RB rows in both phases.
template<int DIN, int RATE,
         int RB1, int CC1, int CW1, int CPT1,
         int RB2, int CC2, int CW2, int CPT2, int PH2X>
__global__ void __launch_bounds__(NTHR, 2) layer_kernel(
    const float* __restrict__ xin, long long xs_t, long long xs_b,
    const float2* __restrict__ gkp, const float* __restrict__ gb,
    const float2* __restrict__ ckp, const float* __restrict__ cb,
    float* __restrict__ out, long long os_t, long long os_b)
{
    extern __shared__ float smem[];
    constexpr int R = RATE * BB;
    constexpr int S = TT / RATE;
    constexpr int COLBLKS1 = 1024 / CC1;
    constexpr int NJOBS1 = (R / RB1) * COLBLKS1;
    static_assert(COLBLKS1 == GSIZE, "group size must match ph1 column blocks");
    static_assert(NJOBS1 == NBLK, "one job per block (ph1)");
    static_assert((R / RB2) * (512 / CC2) == NBLK, "one job per block (ph2)");
    static_assert(RB1 == RB2, "phases must share row mapping");

    // zero this block's own rows (L2-only stores; duplicated within group)
    zero_h_rows<RB1, COLBLKS1, NJOBS1>();
    {
        BarTok tk = bar_arrive();
        prestage_x<DIN, RATE, RB1, CC1, 1024>(xin, xs_t, xs_b, 0, smem);
        bar_wait(tk);
    }

    for (int s = 0; s < S; s++) {
        run_phase<DIN, RATE, RB1, CC1, CW1, CPT1, 1024, 1, 1>(
            xin, xs_t, xs_b, gkp, gb, out, os_t, os_b, s, smem);
        {
            BarTok tk = bar_arrive();
            if (PH2X == 1)
                prestage_x<DIN, RATE, RB2, CC2, 512>(xin, xs_t, xs_b, s, smem);
            bar_wait(tk);
        }
        run_phase<DIN, RATE, RB2, CC2, CW2, CPT2, 512, 2, PH2X>(
            xin, xs_t, xs_b, ckp, cb, out, os_t, os_b, s, smem);
        {
            BarTok tk = bar_arrive();
            if (s + 1 < S)
                prestage_x<DIN, RATE, RB1, CC1, 1024>(xin, xs_t, xs_b, s + 1, smem);
            bar_wait(tk);
        }
    }
}

// states[l][b][:] = layer-l output at time T-1
__global__ void states_kernel(const float* __restrict__ out2, float* __restrict__ st) {
    const int idx = blockIdx.x * blockDim.x + threadIdx.x;
    if (idx >= 3 * BB * HH) return;
    const int l = idx / (BB * HH);
    const int r = idx - l * (BB * HH);
    const int b = r / HH;
    const int n = r - b * HH;
    float v;
    if (l == 0)      v = g_buf0[((size_t)(TT - 1) * BB + b) * HH + n];
    else if (l == 1) v = g_buf1[((size_t)(TT - 1) * BB + b) * HH + n];
    else             v = out2[(size_t)b * TT * HH + (size_t)(TT - 1) * HH + n];
    st[idx] = v;
}

extern "C" void kernel_launch(void* const* d_in, const int* in_sizes, int n_in,
                              void* d_out, int out_size) {
    const float* x   = (const float*)d_in[0];
    const float* gk0 = (const float*)d_in[1];
    const float* gb0 = (const float*)d_in[2];
    const float* ck0 = (const float*)d_in[3];
    const float* cb0 = (const float*)d_in[4];
    const float* gk1 = (const float*)d_in[5];
    const float* gb1 = (const float*)d_in[6];
    const float* ck1 = (const float*)d_in[7];
    const float* cb1 = (const float*)d_in[8];
    const float* gk2 = (const float*)d_in[9];
    const float* gb2 = (const float*)d_in[10];
    const float* ck2 = (const float*)d_in[11];
    const float* cb2 = (const float*)d_in[12];

    float* out = (float*)d_out;
    float* st  = out + (size_t)BB * TT * HH;

    float *buf0 = nullptr, *buf1 = nullptr;
    cudaGetSymbolAddress((void**)&buf0, g_buf0);
    cudaGetSymbolAddress((void**)&buf1, g_buf1);
    float2 *gk0p, *ck0p, *gk1p, *ck1p, *gk2p, *ck2p;
    cudaGetSymbolAddress((void**)&gk0p, g_gk0p);
    cudaGetSymbolAddress((void**)&ck0p, g_ck0p);
    cudaGetSymbolAddress((void**)&gk1p, g_gk1p);
    cudaGetSymbolAddress((void**)&ck1p, g_ck1p);
    cudaGetSymbolAddress((void**)&gk2p, g_gk2p);
    cudaGetSymbolAddress((void**)&ck2p, g_ck2p);

    // Weight repack: 3 fused launches (one per layer).
    pack_weights2_kernel<<<256, 256>>>(gk0, gk0p, 768 / 2, 1024,
                                       ck0, ck0p, 768 / 2, 512);
    pack_weights2_kernel<<<256, 256>>>(gk1, gk1p, 1024 / 2, 1024,
                                       ck1, ck1p, 1024 / 2, 512);
    pack_weights2_kernel<<<256, 256>>>(gk2, gk2p, 1024 / 2, 1024,
                                       ck2, ck2p, 1024 / 2, 512);

    // R16 restructure: 256 blocks x 256 threads, 2 CTAs/SM. 16 independent
    // row-groups of 16 blocks; co-resident blocks of different groups hide
    // each other's barrier + memory latency (the measured binder).
    //  k0: RB4,  smem = op 12KB + red 8KB  = 20480
    //  k1: RB8,  smem = op 32KB + red 16KB = 49152
    //  k2: RB16, smem = op 64KB + red 32KB = 98304  (2x fits 227KB/SM)
    auto k0 = layer_kernel<256, 1,  4, 64, 1, 2,  4, 32, 1, 1, 1>;
    auto k1 = layer_kernel<512, 2,  8, 64, 1, 2,  8, 32, 1, 1, 2>;
    auto k2 = layer_kernel<512, 4, 16, 64, 1, 2, 16, 32, 1, 1, 1>;
    cudaFuncSetAttribute(k0, cudaFuncAttributeMaxDynamicSharedMemorySize, 20480);
    cudaFuncSetAttribute(k1, cudaFuncAttributeMaxDynamicSharedMemorySize, 49152);
    cudaFuncSetAttribute(k2, cudaFuncAttributeMaxDynamicSharedMemorySize, 98304);

    // Layer 0 input: x is [B, T, 256] batch-major -> xs_t=256, xs_b=T*256.
    k0<<<NBLK, NTHR, 20480>>>(x, 256LL, (long long)TT * 256,
                              gk0p, gb0, ck0p, cb0,
                              buf0, (long long)BB * HH, (long long)HH);
    // Layers 1/2 input: time-major [T][B][512] -> xs_t=B*512, xs_b=512.
    k1<<<NBLK, NTHR, 49152>>>(buf0, (long long)BB * HH, 512LL,
                              gk1p, gb1, ck1p, cb1,
                              buf1, (long long)BB * HH, (long long)HH);
    // Final layer writes straight into d_out batch-major [B][T][512].
    k2<<<NBLK, NTHR, 98304>>>(buf1, (long long)BB * HH, 512LL,
                              gk2p, gb2, ck2p, cb2,
                              out, 512LL, (long long)TT * HH);

    if (out_size >= (int)((size_t)BB * TT * HH + 3 * BB * HH)) {
        states_kernel<<<(3 * BB * HH + 255) / 256, 256>>>(out, st);
    }
}